// round 13
// baseline (speedup 1.0000x reference)
#include <cuda_runtime.h>
#include <math.h>
#include <stdint.h>

#define DIM   2048
#define NH    16
#define NKV   4
#define HD    128
#define BB    2
#define SL    2048
#define MROWS (BB*SL)                 // 4096
#define QKV_N ((NH + 2*NKV)*HD)       // 3072

// ---------------- scratch (static device globals; no allocations) -----------
__device__ float g_qkv [MROWS * QKV_N];        // fp32
__device__ float g_q   [BB*NH *SL*HD];         // tf32 values
__device__ float g_k   [BB*NKV*SL*HD];         // tf32
__device__ float g_vt  [BB*NKV*HD*SL];         // tf32, transposed [b][kv][d][s]
__device__ float g_attn[MROWS * DIM];          // tf32
__device__ float g_xc  [MROWS * DIM];          // tf32 copy of x
__device__ float g_wqc [QKV_N * DIM];          // tf32 copy of wqkv
__device__ float g_woc [DIM   * DIM];          // tf32 copy of wo

__device__ __forceinline__ float to_tf32(float x) {
    float r;
    asm("cvt.rna.tf32.f32 %0, %1;" : "=f"(r) : "f"(x));
    return r;
}

__device__ __forceinline__ void mma_tf32(float c[4],
                                         uint32_t a0, uint32_t a1,
                                         uint32_t a2, uint32_t a3,
                                         uint32_t b0, uint32_t b1) {
    asm volatile(
        "mma.sync.aligned.m16n8k8.row.col.f32.tf32.tf32.f32 "
        "{%0,%1,%2,%3},{%4,%5,%6,%7},{%8,%9},{%0,%1,%2,%3};"
        : "+f"(c[0]), "+f"(c[1]), "+f"(c[2]), "+f"(c[3])
        : "r"(a0), "r"(a1), "r"(a2), "r"(a3), "r"(b0), "r"(b1));
}

__device__ __forceinline__ void ldsm4(uint32_t& r0, uint32_t& r1,
                                      uint32_t& r2, uint32_t& r3,
                                      uint32_t addr) {
    asm volatile("ldmatrix.sync.aligned.m8n8.x4.shared.b16 {%0,%1,%2,%3}, [%4];"
                 : "=r"(r0), "=r"(r1), "=r"(r2), "=r"(r3) : "r"(addr));
}

__device__ __forceinline__ void cp16(void* smem, const float* g) {
    uint32_t s = (uint32_t)__cvta_generic_to_shared(smem);
    asm volatile("cp.async.cg.shared.global [%0], [%1], 16;"
                 :: "r"(s), "l"(g) : "memory");
}
#define CP_COMMIT() asm volatile("cp.async.commit_group;" ::: "memory")
#define CP_WAIT1()  asm volatile("cp.async.wait_group 1;"  ::: "memory")
#define CP_WAIT0()  asm volatile("cp.async.wait_group 0;"  ::: "memory")

// ---------------------------------------------------------------------------
// Merged fp32 -> tf32 convert for all three GEMM operands (one launch).
// ---------------------------------------------------------------------------
__global__ void conv3_tf32(const float* __restrict__ x,
                           const float* __restrict__ wq,
                           const float* __restrict__ wo) {
    const int gs = gridDim.x * blockDim.x;
    const int t  = blockIdx.x * blockDim.x + threadIdx.x;
    const int n1 = MROWS * DIM / 4, n2 = QKV_N * DIM / 4, n3 = DIM * DIM / 4;

    for (int i = t; i < n1; i += gs) {
        float4 v = ((const float4*)x)[i];
        v.x = to_tf32(v.x); v.y = to_tf32(v.y);
        v.z = to_tf32(v.z); v.w = to_tf32(v.w);
        ((float4*)g_xc)[i] = v;
    }
    for (int i = t; i < n2; i += gs) {
        float4 v = ((const float4*)wq)[i];
        v.x = to_tf32(v.x); v.y = to_tf32(v.y);
        v.z = to_tf32(v.z); v.w = to_tf32(v.w);
        ((float4*)g_wqc)[i] = v;
    }
    for (int i = t; i < n3; i += gs) {
        float4 v = ((const float4*)wo)[i];
        v.x = to_tf32(v.x); v.y = to_tf32(v.y);
        v.z = to_tf32(v.z); v.w = to_tf32(v.w);
        ((float4*)g_woc)[i] = v;
    }
}

// ---------------------------------------------------------------------------
// C = A * B^T, tf32 mma.sync. CTA tile 128x256, warp tile 64x64 (8 warps),
// 3-stage cp.async, ldmatrix frags. Pitch 36.  (unchanged from R12)
// ---------------------------------------------------------------------------
#define GP      36
#define ASTG    (128 * GP)
#define BSTG    (256 * GP)
#define STG_TOT (ASTG + BSTG)
#define GEMM_SMEM (3 * STG_TOT * 4)            // 165888 B

__global__ __launch_bounds__(256, 1)
void sgemm_tf32(const float* __restrict__ A, const float* __restrict__ B,
                float* __restrict__ C, int M, int N, int K) {
    extern __shared__ float sm[];
    const uint32_t sbase = (uint32_t)__cvta_generic_to_shared(sm);

    const int tid  = threadIdx.x;
    const int lane = tid & 31;
    const int warp = tid >> 5;
    const int wm   = warp & 1;
    const int wn   = warp >> 1;
    const int gid  = lane >> 2;
    const int tig  = lane & 3;
    const int l8   = lane & 7;
    const int g8   = lane >> 3;

    const int m0 = blockIdx.y * 128;
    const int n0 = blockIdx.x * 256;
    const float* Ab = A + (size_t)m0 * K;
    const float* Bb = B + (size_t)n0 * K;

    const int fr = tid >> 3;
    const int ck = (tid & 7) << 2;

    const uint32_t offA = (uint32_t)(((wm * 64 + l8 + (g8 & 1) * 8) * GP
                                      + (g8 >> 1) * 4) * 4);
    const uint32_t offB = (uint32_t)(((wn * 64 + l8 + (g8 >> 1) * 8) * GP
                                      + (g8 & 1) * 4) * 4);

    float c[4][8][4] = {};
    const int nch = K / 32;

#define G_FILL(buf, k0)                                                       \
    {                                                                         \
        float* As_ = sm + (buf) * STG_TOT;                                    \
        float* Bs_ = As_ + ASTG;                                              \
        _Pragma("unroll")                                                     \
        for (int i = 0; i < 4; i++) {                                         \
            int r = fr + i * 32;                                              \
            cp16(As_ + r * GP + ck, Ab + (size_t)r * K + (k0) + ck);          \
        }                                                                     \
        _Pragma("unroll")                                                     \
        for (int i = 0; i < 8; i++) {                                         \
            int r = fr + i * 32;                                              \
            cp16(Bs_ + r * GP + ck, Bb + (size_t)r * K + (k0) + ck);          \
        }                                                                     \
    }

    G_FILL(0, 0);  CP_COMMIT();
    G_FILL(1, 32); CP_COMMIT();

    for (int ch = 0; ch < nch; ch++) {
        const int buf = ch % 3;
        if (ch + 1 < nch) CP_WAIT1(); else CP_WAIT0();
        __syncthreads();

        const uint32_t sA = sbase + (uint32_t)(buf * STG_TOT) * 4u;
        const uint32_t sB = sA + (uint32_t)ASTG * 4u;

#pragma unroll
        for (int kk = 0; kk < 32; kk += 8) {
            uint32_t a[4][4], b[8][2];
#pragma unroll
            for (int f = 0; f < 4; f++)
                ldsm4(a[f][0], a[f][1], a[f][2], a[f][3],
                      sA + offA + (uint32_t)((f * 16 * GP + kk) * 4));
#pragma unroll
            for (int gp = 0; gp < 4; gp++)
                ldsm4(b[2 * gp][0], b[2 * gp][1],
                      b[2 * gp + 1][0], b[2 * gp + 1][1],
                      sB + offB + (uint32_t)((gp * 16 * GP + kk) * 4));
#pragma unroll
            for (int f = 0; f < 4; f++)
#pragma unroll
                for (int g = 0; g < 8; g++)
                    mma_tf32(c[f][g], a[f][0], a[f][1], a[f][2], a[f][3],
                             b[g][0], b[g][1]);
        }

        if (ch + 2 < nch) { G_FILL((ch + 2) % 3, (ch + 2) * 32); CP_COMMIT(); }
    }

#pragma unroll
    for (int f = 0; f < 4; f++) {
        int row = m0 + wm * 64 + f * 16 + gid;
#pragma unroll
        for (int g = 0; g < 8; g++) {
            int col = n0 + wn * 64 + g * 8 + 2 * tig;
            *(float2*)&C[(size_t)row * N + col] =
                make_float2(c[f][g][0], c[f][g][1]);
            *(float2*)&C[(size_t)(row + 8) * N + col] =
                make_float2(c[f][g][2], c[f][g][3]);
        }
    }
}

// ---------------------------------------------------------------------------
// RMSNorm + RoPE, one warp per (token, head) vector; outputs tf32.
// V written TRANSPOSED to g_vt [b][kv][d][s] (PV uses ldmatrix on V^T).
// ---------------------------------------------------------------------------
__global__ __launch_bounds__(256)
void norm_rope(const float* __restrict__ qnw, const float* __restrict__ knw,
               const float* __restrict__ fcos, const float* __restrict__ fsin) {
    const int lane = threadIdx.x & 31;
    const int widx = blockIdx.x * 8 + (threadIdx.x >> 5);
    const int hh = widx % 24;
    const int m  = widx / 24;
    const int b  = m / SL;
    const int s  = m % SL;
    const int d4 = lane * 4;

    float4 v = *(const float4*)&g_qkv[(size_t)m * QKV_N + hh * HD + d4];

    if (hh < 20) {
        float ssq = v.x * v.x + v.y * v.y + v.z * v.z + v.w * v.w;
#pragma unroll
        for (int o = 16; o > 0; o >>= 1)
            ssq += __shfl_xor_sync(0xffffffffu, ssq, o);
        float r = rsqrtf(ssq * (1.0f / HD) + 1.1920929e-07f);

        const float* w = (hh < NH) ? qnw : knw;
        float4 wv = *(const float4*)&w[d4];
        float x0 = v.x * r * wv.x, x1 = v.y * r * wv.y;
        float x2 = v.z * r * wv.z, x3 = v.w * r * wv.w;

        float4 fc = *(const float4*)&fcos[s * HD + d4];
        float4 fs = *(const float4*)&fsin[s * HD + d4];
        float4 o;
        o.x = to_tf32(x0 * fc.x - x1 * fs.x);
        o.y = to_tf32(x1 * fc.y + x0 * fs.y);
        o.z = to_tf32(x2 * fc.z - x3 * fs.z);
        o.w = to_tf32(x3 * fc.w + x2 * fs.w);

        if (hh < NH)
            *(float4*)&g_q[(((size_t)b * NH  + hh)      * SL + s) * HD + d4] = o;
        else
            *(float4*)&g_k[(((size_t)b * NKV + (hh-16)) * SL + s) * HD + d4] = o;
    } else {
        float* base = g_vt + (((size_t)b * NKV + (hh - 20)) * HD + d4) * SL + s;
        base[0 * SL] = to_tf32(v.x);
        base[1 * SL] = to_tf32(v.y);
        base[2 * SL] = to_tf32(v.z);
        base[3 * SL] = to_tf32(v.w);
    }
}

// ---------------------------------------------------------------------------
// Flash attention, tf32 mma.sync, NO-MAX softmax, CROSS-TILE PIPELINE:
// S(kt+1) MMAs interleaved with softmax(kt) so the tensor pipe stays fed
// during the MUFU/cvt phase. K double-buffered, V^T triple-buffered.
// QT=128 (8 warps x 16 rows), KT=64.
// ---------------------------------------------------------------------------
#define FQT  128
#define FKT  64
#define KP   132
#define VTP  68
#define KBUF(b) ((b) * FKT * KP)
#define VBUF(b) (2 * FKT * KP + (b) * HD * VTP)
#define FLASH_SMEM ((2 * FKT * KP + 3 * HD * VTP) * 4)   // 172032 B

__global__ __launch_bounds__(256)
void flash_tf32() {
    extern __shared__ float sm[];
    const uint32_t sbase = (uint32_t)__cvta_generic_to_shared(sm);

    const int tid  = threadIdx.x;
    const int lane = tid & 31;
    const int warp = tid >> 5;
    const int gid  = lane >> 2;
    const int tig  = lane & 3;
    const int l8   = lane & 7;
    const int g8   = lane >> 3;
    const int wq   = warp * 16;

    const int qt = blockIdx.x, h = blockIdx.y, b = blockIdx.z;
    const int kvh = h >> 2;

    const float* Qg  = g_q  + (((size_t)b * NH  + h  ) * SL + qt * FQT) * HD;
    const float* Kg  = g_k  + (((size_t)b * NKV + kvh) * SL) * HD;
    const float* Vtg = g_vt + (((size_t)b * NKV + kvh) * HD) * SL;

    const float qscale = 1.4426950408889634f * rsqrtf((float)HD);

    // ---- stage Q (aliases the two K buffers), frag-load via ldmatrix ----
    float* Qb = sm;
#pragma unroll
    for (int it = 0; it < 16; it++) {
        int idx = tid + it * 256;
        int r = idx >> 5, c = (idx & 31) << 2;
        float4 v = *(const float4*)(Qg + (size_t)r * HD + c);
        Qb[r * KP + c + 0] = to_tf32(v.x * qscale);
        Qb[r * KP + c + 1] = to_tf32(v.y * qscale);
        Qb[r * KP + c + 2] = to_tf32(v.z * qscale);
        Qb[r * KP + c + 3] = to_tf32(v.w * qscale);
    }
    __syncthreads();

    const uint32_t offQ = (uint32_t)(((wq + l8 + (g8 & 1) * 8) * KP
                                      + (g8 >> 1) * 4) * 4);
    uint32_t qa[16][4];
#pragma unroll
    for (int ks = 0; ks < 16; ks++)
        ldsm4(qa[ks][0], qa[ks][1], qa[ks][2], qa[ks][3],
              sbase + offQ + (uint32_t)(8 * ks * 4));
    __syncthreads();   // Q reads done before cp.async overwrites the alias

    float c[16][4] = {};
    float l0 = 0.0f, l1 = 0.0f;

    const int srcA = (gid << 2) + (tig >> 1);
    const int srcB = srcA + 2;
    const bool odd = (tig & 1) != 0;

    const int kr = tid >> 5, kc = (tid & 31) << 2;   // K copy map
    const int vr = tid >> 4, vc = (tid & 15) << 2;   // Vt copy map

    const uint32_t offK = (uint32_t)(((l8 + (g8 >> 1) * 8) * KP
                                      + (g8 & 1) * 4) * 4);
    const uint32_t offV = (uint32_t)(((l8 + (g8 >> 1) * 8) * VTP
                                      + (g8 & 1) * 4) * 4);

    const int NKT = SL / FKT;

#define F_FILL(t)                                                             \
    {                                                                         \
        const float* Kn  = Kg  + (size_t)(t) * FKT * HD;                      \
        const float* Vtn = Vtg + (size_t)(t) * FKT;                           \
        float* kb = sm + KBUF((t) & 1);                                       \
        float* vb = sm + VBUF((t) % 3);                                       \
        _Pragma("unroll")                                                     \
        for (int it = 0; it < 8; it++) {                                      \
            int r = kr + it * 8;                                              \
            cp16(kb + r * KP + kc, Kn + (size_t)r * HD + kc);                 \
        }                                                                     \
        _Pragma("unroll")                                                     \
        for (int it = 0; it < 8; it++) {                                      \
            int d = vr + it * 16;                                             \
            cp16(vb + d * VTP + vc, Vtn + (size_t)d * SL + vc);               \
        }                                                                     \
    }

#define SOFTMAX4(scX, j)                                                      \
    {                                                                         \
        float p0 = exp2f(scX[j][0]), p1 = exp2f(scX[j][1]);                   \
        float p2 = exp2f(scX[j][2]), p3 = exp2f(scX[j][3]);                   \
        l0 += p0 + p1; l1 += p2 + p3;                                         \
        scX[j][0] = to_tf32(p0); scX[j][1] = to_tf32(p1);                     \
        scX[j][2] = to_tf32(p2); scX[j][3] = to_tf32(p3);                     \
    }

    float sc0[8][4], sc1[8][4];

    // prologue: fill tiles 0 and 1; compute S(0)
    F_FILL(0); CP_COMMIT();
    F_FILL(1); CP_COMMIT();
    CP_WAIT1();                 // tile 0 resident
    __syncthreads();
    {
        const uint32_t sK = sbase + (uint32_t)(KBUF(0) * 4);
#pragma unroll
        for (int j = 0; j < 8; j++)
#pragma unroll
            for (int q = 0; q < 4; q++) sc0[j][q] = 0.0f;
#pragma unroll
        for (int ks = 0; ks < 16; ks++)
#pragma unroll
            for (int jp = 0; jp < 4; jp++) {
                uint32_t b0, b1, b2, b3;
                ldsm4(b0, b1, b2, b3,
                      sK + offK + (uint32_t)((jp * 16 * KP + 8 * ks) * 4));
                mma_tf32(sc0[2 * jp],     qa[ks][0], qa[ks][1], qa[ks][2], qa[ks][3], b0, b1);
                mma_tf32(sc0[2 * jp + 1], qa[ks][0], qa[ks][1], qa[ks][2], qa[ks][3], b2, b3);
            }
    }

#define TILE_BODY(kt, scC, scN)                                               \
    {                                                                         \
        const int last = ((kt) == NKT - 1);                                   \
        if (!last) CP_WAIT0();                                                \
        __syncthreads();                                                      \
        if (!last) {                                                          \
            const uint32_t sKn = sbase + (uint32_t)(KBUF(((kt) + 1) & 1) * 4);\
            _Pragma("unroll")                                                 \
            for (int j = 0; j < 8; j++)                                       \
                _Pragma("unroll")                                             \
                for (int q = 0; q < 4; q++) scN[j][q] = 0.0f;                 \
            _Pragma("unroll")                                                 \
            for (int ks = 0; ks < 16; ks++) {                                 \
                _Pragma("unroll")                                             \
                for (int jp = 0; jp < 4; jp++) {                              \
                    uint32_t b0, b1, b2, b3;                                  \
                    ldsm4(b0, b1, b2, b3,                                     \
                          sKn + offK + (uint32_t)((jp * 16 * KP + 8 * ks) * 4)); \
                    mma_tf32(scN[2 * jp],     qa[ks][0], qa[ks][1], qa[ks][2], qa[ks][3], b0, b1); \
                    mma_tf32(scN[2 * jp + 1], qa[ks][0], qa[ks][1], qa[ks][2], qa[ks][3], b2, b3); \
                }                                                             \
                if (ks < 8) SOFTMAX4(scC, ks);                                \
            }                                                                 \
        } else {                                                              \
            _Pragma("unroll")                                                 \
            for (int j = 0; j < 8; j++) SOFTMAX4(scC, j);                     \
        }                                                                     \
        if ((kt) + 2 < NKT) { F_FILL((kt) + 2); CP_COMMIT(); }                \
        const uint32_t sV = sbase + (uint32_t)(VBUF((kt) % 3) * 4);           \
        _Pragma("unroll")                                                     \
        for (int j = 0; j < 8; j++) {                                         \
            float v0 = __shfl_sync(0xffffffffu, scC[j][0], srcA);             \
            float v1 = __shfl_sync(0xffffffffu, scC[j][1], srcA);             \
            float v2 = __shfl_sync(0xffffffffu, scC[j][2], srcA);             \
            float v3 = __shfl_sync(0xffffffffu, scC[j][3], srcA);             \
            float w0 = __shfl_sync(0xffffffffu, scC[j][0], srcB);             \
            float w1 = __shfl_sync(0xffffffffu, scC[j][1], srcB);             \
            float w2 = __shfl_sync(0xffffffffu, scC[j][2], srcB);             \
            float w3 = __shfl_sync(0xffffffffu, scC[j][3], srcB);             \
            uint32_t a0 = __float_as_uint(odd ? v1 : v0);                     \
            uint32_t a1 = __float_as_uint(odd ? v3 : v2);                     \
            uint32_t a2 = __float_as_uint(odd ? w1 : w0);                     \
            uint32_t a3 = __float_as_uint(odd ? w3 : w2);                     \
            _Pragma("unroll")                                                 \
            for (int jp = 0; jp < 8; jp++) {                                  \
                uint32_t b0, b1, b2, b3;                                      \
                ldsm4(b0, b1, b2, b3,                                         \
                      sV + offV + (uint32_t)((jp * 16 * VTP + 8 * j) * 4));   \
                mma_tf32(c[2 * jp],     a0, a1, a2, a3, b0, b1);              \
                mma_tf32(c[2 * jp + 1], a0, a1, a2, a3, b2, b3);              \
            }                                                                 \
        }                                                                     \
    }

    for (int kt2 = 0; kt2 < NKT; kt2 += 2) {
        TILE_BODY(kt2,     sc0, sc1);
        TILE_BODY(kt2 + 1, sc1, sc0);
    }

    // ---- final l reduction across the quad, normalize + write ----
    l0 += __shfl_xor_sync(0xffffffffu, l0, 1);
    l0 += __shfl_xor_sync(0xffffffffu, l0, 2);
    l1 += __shfl_xor_sync(0xffffffffu, l1, 1);
    l1 += __shfl_xor_sync(0xffffffffu, l1, 2);
    float inv0 = 1.0f / l0, inv1 = 1.0f / l1;
    int row0 = qt * FQT + wq + gid;
#pragma unroll
    for (int j2 = 0; j2 < 16; j2++) {
        int col = h * HD + 8 * j2 + 2 * tig;
        *(float2*)&g_attn[((size_t)b * SL + row0) * DIM + col] =
            make_float2(to_tf32(c[j2][0] * inv0), to_tf32(c[j2][1] * inv0));
        *(float2*)&g_attn[((size_t)b * SL + row0 + 8) * DIM + col] =
            make_float2(to_tf32(c[j2][2] * inv1), to_tf32(c[j2][3] * inv1));
    }
}

// ---------------------------------------------------------------------------
extern "C" void kernel_launch(void* const* d_in, const int* in_sizes, int n_in,
                              void* d_out, int out_size) {
    const float* x    = (const float*)d_in[0];
    const float* wqkv = (const float*)d_in[1];
    const float* wo   = (const float*)d_in[2];
    const float* qnw  = (const float*)d_in[3];
    const float* knw  = (const float*)d_in[4];
    const float* fcos = (const float*)d_in[5];
    const float* fsin = (const float*)d_in[6];
    float* out = (float*)d_out;

    void *p_qkv, *p_attn, *p_xc, *p_wqc, *p_woc;
    cudaGetSymbolAddress(&p_qkv,  g_qkv);
    cudaGetSymbolAddress(&p_attn, g_attn);
    cudaGetSymbolAddress(&p_xc,   g_xc);
    cudaGetSymbolAddress(&p_wqc,  g_wqc);
    cudaGetSymbolAddress(&p_woc,  g_woc);

    cudaFuncSetAttribute(flash_tf32,
                         cudaFuncAttributeMaxDynamicSharedMemorySize, FLASH_SMEM);
    cudaFuncSetAttribute(sgemm_tf32,
                         cudaFuncAttributeMaxDynamicSharedMemorySize, GEMM_SMEM);

    // 0) pre-convert all GEMM operands to tf32 (single launch)
    conv3_tf32<<<1184, 256>>>(x, wqkv, wo);

    // 1) QKV projection
    sgemm_tf32<<<dim3(QKV_N / 256, MROWS / 128), 256, GEMM_SMEM>>>(
        (const float*)p_xc, (const float*)p_wqc, (float*)p_qkv,
        MROWS, QKV_N, DIM);

    // 2) RMSNorm + RoPE (V transposed)
    norm_rope<<<MROWS * 24 / 8, 256>>>(qnw, knw, fcos, fsin);

    // 3) Flash attention (cross-tile pipelined)
    flash_tf32<<<dim3(SL / FQT, NH, BB), 256, FLASH_SMEM>>>();

    // 4) Output projection
    sgemm_tf32<<<dim3(DIM / 256, MROWS / 128), 256, GEMM_SMEM>>>(
        (const float*)p_attn, (const float*)p_woc, out, MROWS, DIM, DIM);
}

// round 14
// speedup vs baseline: 1.0044x; 1.0044x over previous
#include <cuda_runtime.h>
#include <math.h>
#include <stdint.h>

#define DIM   2048
#define NH    16
#define NKV   4
#define HD    128
#define BB    2
#define SL    2048
#define MROWS (BB*SL)                 // 4096
#define QKV_N ((NH + 2*NKV)*HD)       // 3072

// ---------------- scratch (static device globals; no allocations) -----------
__device__ float g_qkv [MROWS * QKV_N];        // fp32
__device__ float g_q   [BB*NH *SL*HD];         // tf32 values
__device__ float g_k   [BB*NKV*SL*HD];         // tf32
__device__ float g_vt  [BB*NKV*HD*SL];         // tf32, transposed [b][kv][d][s]
__device__ float g_attn[MROWS * DIM];          // tf32
__device__ float g_xc  [MROWS * DIM];          // tf32 copy of x
__device__ float g_wqc [QKV_N * DIM];          // tf32 copy of wqkv
__device__ float g_woc [DIM   * DIM];          // tf32 copy of wo

__device__ __forceinline__ float to_tf32(float x) {
    float r;
    asm("cvt.rna.tf32.f32 %0, %1;" : "=f"(r) : "f"(x));
    return r;
}

__device__ __forceinline__ void mma_tf32(float c[4],
                                         uint32_t a0, uint32_t a1,
                                         uint32_t a2, uint32_t a3,
                                         uint32_t b0, uint32_t b1) {
    asm volatile(
        "mma.sync.aligned.m16n8k8.row.col.f32.tf32.tf32.f32 "
        "{%0,%1,%2,%3},{%4,%5,%6,%7},{%8,%9},{%0,%1,%2,%3};"
        : "+f"(c[0]), "+f"(c[1]), "+f"(c[2]), "+f"(c[3])
        : "r"(a0), "r"(a1), "r"(a2), "r"(a3), "r"(b0), "r"(b1));
}

__device__ __forceinline__ void ldsm4(uint32_t& r0, uint32_t& r1,
                                      uint32_t& r2, uint32_t& r3,
                                      uint32_t addr) {
    asm volatile("ldmatrix.sync.aligned.m8n8.x4.shared.b16 {%0,%1,%2,%3}, [%4];"
                 : "=r"(r0), "=r"(r1), "=r"(r2), "=r"(r3) : "r"(addr));
}

__device__ __forceinline__ void cp16(void* smem, const float* g) {
    uint32_t s = (uint32_t)__cvta_generic_to_shared(smem);
    asm volatile("cp.async.cg.shared.global [%0], [%1], 16;"
                 :: "r"(s), "l"(g) : "memory");
}
#define CP_COMMIT() asm volatile("cp.async.commit_group;" ::: "memory")
#define CP_WAIT1()  asm volatile("cp.async.wait_group 1;"  ::: "memory")
#define CP_WAIT0()  asm volatile("cp.async.wait_group 0;"  ::: "memory")

// ---------------------------------------------------------------------------
// Merged fp32 -> tf32 convert for all three GEMM operands (one launch).
// ---------------------------------------------------------------------------
__global__ void conv3_tf32(const float* __restrict__ x,
                           const float* __restrict__ wq,
                           const float* __restrict__ wo) {
    const int gs = gridDim.x * blockDim.x;
    const int t  = blockIdx.x * blockDim.x + threadIdx.x;
    const int n1 = MROWS * DIM / 4, n2 = QKV_N * DIM / 4, n3 = DIM * DIM / 4;

    for (int i = t; i < n1; i += gs) {
        float4 v = ((const float4*)x)[i];
        v.x = to_tf32(v.x); v.y = to_tf32(v.y);
        v.z = to_tf32(v.z); v.w = to_tf32(v.w);
        ((float4*)g_xc)[i] = v;
    }
    for (int i = t; i < n2; i += gs) {
        float4 v = ((const float4*)wq)[i];
        v.x = to_tf32(v.x); v.y = to_tf32(v.y);
        v.z = to_tf32(v.z); v.w = to_tf32(v.w);
        ((float4*)g_wqc)[i] = v;
    }
    for (int i = t; i < n3; i += gs) {
        float4 v = ((const float4*)wo)[i];
        v.x = to_tf32(v.x); v.y = to_tf32(v.y);
        v.z = to_tf32(v.z); v.w = to_tf32(v.w);
        ((float4*)g_woc)[i] = v;
    }
}

// ---------------------------------------------------------------------------
// C = A * B^T, tf32 mma.sync. CTA tile 128x256, warp tile 64x64 (8 warps),
// 3-stage cp.async, ldmatrix frags. Pitch 36.  (unchanged from R12)
// ---------------------------------------------------------------------------
#define GP      36
#define ASTG    (128 * GP)
#define BSTG    (256 * GP)
#define STG_TOT (ASTG + BSTG)
#define GEMM_SMEM (3 * STG_TOT * 4)            // 165888 B

__global__ __launch_bounds__(256, 1)
void sgemm_tf32(const float* __restrict__ A, const float* __restrict__ B,
                float* __restrict__ C, int M, int N, int K) {
    extern __shared__ float sm[];
    const uint32_t sbase = (uint32_t)__cvta_generic_to_shared(sm);

    const int tid  = threadIdx.x;
    const int lane = tid & 31;
    const int warp = tid >> 5;
    const int wm   = warp & 1;
    const int wn   = warp >> 1;
    const int gid  = lane >> 2;
    const int tig  = lane & 3;
    const int l8   = lane & 7;
    const int g8   = lane >> 3;

    const int m0 = blockIdx.y * 128;
    const int n0 = blockIdx.x * 256;
    const float* Ab = A + (size_t)m0 * K;
    const float* Bb = B + (size_t)n0 * K;

    const int fr = tid >> 3;
    const int ck = (tid & 7) << 2;

    const uint32_t offA = (uint32_t)(((wm * 64 + l8 + (g8 & 1) * 8) * GP
                                      + (g8 >> 1) * 4) * 4);
    const uint32_t offB = (uint32_t)(((wn * 64 + l8 + (g8 >> 1) * 8) * GP
                                      + (g8 & 1) * 4) * 4);

    float c[4][8][4] = {};
    const int nch = K / 32;

#define G_FILL(buf, k0)                                                       \
    {                                                                         \
        float* As_ = sm + (buf) * STG_TOT;                                    \
        float* Bs_ = As_ + ASTG;                                              \
        _Pragma("unroll")                                                     \
        for (int i = 0; i < 4; i++) {                                         \
            int r = fr + i * 32;                                              \
            cp16(As_ + r * GP + ck, Ab + (size_t)r * K + (k0) + ck);          \
        }                                                                     \
        _Pragma("unroll")                                                     \
        for (int i = 0; i < 8; i++) {                                         \
            int r = fr + i * 32;                                              \
            cp16(Bs_ + r * GP + ck, Bb + (size_t)r * K + (k0) + ck);          \
        }                                                                     \
    }

    G_FILL(0, 0);  CP_COMMIT();
    G_FILL(1, 32); CP_COMMIT();

    for (int ch = 0; ch < nch; ch++) {
        const int buf = ch % 3;
        if (ch + 1 < nch) CP_WAIT1(); else CP_WAIT0();
        __syncthreads();

        const uint32_t sA = sbase + (uint32_t)(buf * STG_TOT) * 4u;
        const uint32_t sB = sA + (uint32_t)ASTG * 4u;

#pragma unroll
        for (int kk = 0; kk < 32; kk += 8) {
            uint32_t a[4][4], b[8][2];
#pragma unroll
            for (int f = 0; f < 4; f++)
                ldsm4(a[f][0], a[f][1], a[f][2], a[f][3],
                      sA + offA + (uint32_t)((f * 16 * GP + kk) * 4));
#pragma unroll
            for (int gp = 0; gp < 4; gp++)
                ldsm4(b[2 * gp][0], b[2 * gp][1],
                      b[2 * gp + 1][0], b[2 * gp + 1][1],
                      sB + offB + (uint32_t)((gp * 16 * GP + kk) * 4));
#pragma unroll
            for (int f = 0; f < 4; f++)
#pragma unroll
                for (int g = 0; g < 8; g++)
                    mma_tf32(c[f][g], a[f][0], a[f][1], a[f][2], a[f][3],
                             b[g][0], b[g][1]);
        }

        if (ch + 2 < nch) { G_FILL((ch + 2) % 3, (ch + 2) * 32); CP_COMMIT(); }
    }

#pragma unroll
    for (int f = 0; f < 4; f++) {
        int row = m0 + wm * 64 + f * 16 + gid;
#pragma unroll
        for (int g = 0; g < 8; g++) {
            int col = n0 + wn * 64 + g * 8 + 2 * tig;
            *(float2*)&C[(size_t)row * N + col] =
                make_float2(c[f][g][0], c[f][g][1]);
            *(float2*)&C[(size_t)(row + 8) * N + col] =
                make_float2(c[f][g][2], c[f][g][3]);
        }
    }
}

// ---------------------------------------------------------------------------
// RMSNorm + RoPE, one warp per (token, head) vector; outputs tf32.
// V written TRANSPOSED to g_vt [b][kv][d][s].
// ---------------------------------------------------------------------------
__global__ __launch_bounds__(256)
void norm_rope(const float* __restrict__ qnw, const float* __restrict__ knw,
               const float* __restrict__ fcos, const float* __restrict__ fsin) {
    const int lane = threadIdx.x & 31;
    const int widx = blockIdx.x * 8 + (threadIdx.x >> 5);
    const int hh = widx % 24;
    const int m  = widx / 24;
    const int b  = m / SL;
    const int s  = m % SL;
    const int d4 = lane * 4;

    float4 v = *(const float4*)&g_qkv[(size_t)m * QKV_N + hh * HD + d4];

    if (hh < 20) {
        float ssq = v.x * v.x + v.y * v.y + v.z * v.z + v.w * v.w;
#pragma unroll
        for (int o = 16; o > 0; o >>= 1)
            ssq += __shfl_xor_sync(0xffffffffu, ssq, o);
        float r = rsqrtf(ssq * (1.0f / HD) + 1.1920929e-07f);

        const float* w = (hh < NH) ? qnw : knw;
        float4 wv = *(const float4*)&w[d4];
        float x0 = v.x * r * wv.x, x1 = v.y * r * wv.y;
        float x2 = v.z * r * wv.z, x3 = v.w * r * wv.w;

        float4 fc = *(const float4*)&fcos[s * HD + d4];
        float4 fs = *(const float4*)&fsin[s * HD + d4];
        float4 o;
        o.x = to_tf32(x0 * fc.x - x1 * fs.x);
        o.y = to_tf32(x1 * fc.y + x0 * fs.y);
        o.z = to_tf32(x2 * fc.z - x3 * fs.z);
        o.w = to_tf32(x3 * fc.w + x2 * fs.w);

        if (hh < NH)
            *(float4*)&g_q[(((size_t)b * NH  + hh)      * SL + s) * HD + d4] = o;
        else
            *(float4*)&g_k[(((size_t)b * NKV + (hh-16)) * SL + s) * HD + d4] = o;
    } else {
        float* base = g_vt + (((size_t)b * NKV + (hh - 20)) * HD + d4) * SL + s;
        base[0 * SL] = to_tf32(v.x);
        base[1 * SL] = to_tf32(v.y);
        base[2 * SL] = to_tf32(v.z);
        base[3 * SL] = to_tf32(v.w);
    }
}

// ---------------------------------------------------------------------------
// Flash attention, tf32 mma.sync, NO-MAX softmax.
// QT=64 (4 warps x 16 rows), KT=32, 128 threads, 3 CTAs/SM (reg-bounded).
// K double-buffered (pitch 132), V^T double-buffered (pitch 36).
// Q staging aliases the two K buffers exactly (64*132 = 2*32*132).
// ---------------------------------------------------------------------------
#define FQT  64
#define FKT  32
#define KP   132
#define VTP  36
#define KBUF(b) ((b) * FKT * KP)                       // 32*132 floats each
#define VBUF(b) (2 * FKT * KP + (b) * HD * VTP)        // 128*36 floats each
#define FLASH_SMEM ((2 * FKT * KP + 2 * HD * VTP) * 4) // 70656 B

__global__ __launch_bounds__(128, 3)
void flash_tf32() {
    extern __shared__ float sm[];
    const uint32_t sbase = (uint32_t)__cvta_generic_to_shared(sm);

    const int tid  = threadIdx.x;
    const int lane = tid & 31;
    const int warp = tid >> 5;          // 0..3
    const int gid  = lane >> 2;
    const int tig  = lane & 3;
    const int l8   = lane & 7;
    const int g8   = lane >> 3;
    const int wq   = warp * 16;

    const int qt = blockIdx.x, h = blockIdx.y, b = blockIdx.z;
    const int kvh = h >> 2;

    const float* Qg  = g_q  + (((size_t)b * NH  + h  ) * SL + qt * FQT) * HD;
    const float* Kg  = g_k  + (((size_t)b * NKV + kvh) * SL) * HD;
    const float* Vtg = g_vt + (((size_t)b * NKV + kvh) * HD) * SL;

    const float qscale = 1.4426950408889634f * rsqrtf((float)HD);

    // ---- stage Q (aliases the two K buffers), frag-load via ldmatrix ----
    float* Qb = sm;
#pragma unroll
    for (int it = 0; it < 16; it++) {
        int idx = tid + it * 128;                  // 0..2047 float4
        int r = idx >> 5, c = (idx & 31) << 2;
        float4 v = *(const float4*)(Qg + (size_t)r * HD + c);
        Qb[r * KP + c + 0] = to_tf32(v.x * qscale);
        Qb[r * KP + c + 1] = to_tf32(v.y * qscale);
        Qb[r * KP + c + 2] = to_tf32(v.z * qscale);
        Qb[r * KP + c + 3] = to_tf32(v.w * qscale);
    }
    __syncthreads();

    const uint32_t offQ = (uint32_t)(((wq + l8 + (g8 & 1) * 8) * KP
                                      + (g8 >> 1) * 4) * 4);
    uint32_t qa[16][4];
#pragma unroll
    for (int ks = 0; ks < 16; ks++)
        ldsm4(qa[ks][0], qa[ks][1], qa[ks][2], qa[ks][3],
              sbase + offQ + (uint32_t)(8 * ks * 4));
    __syncthreads();   // Q reads done before cp.async overwrites the alias

    float c[16][4] = {};
    float l0 = 0.0f, l1 = 0.0f;

    const int srcA = (gid << 2) + (tig >> 1);
    const int srcB = srcA + 2;
    const bool odd = (tig & 1) != 0;

    const uint32_t offK = (uint32_t)(((l8 + (g8 >> 1) * 8) * KP
                                      + (g8 & 1) * 4) * 4);
    const uint32_t offV = (uint32_t)(((l8 + (g8 >> 1) * 8) * VTP
                                      + (g8 & 1) * 4) * 4);

    const int NKT = SL / FKT;                       // 64 tiles

#define F_FILL(t)                                                             \
    {                                                                         \
        const float* Kn  = Kg  + (size_t)(t) * FKT * HD;                      \
        const float* Vtn = Vtg + (size_t)(t) * FKT;                           \
        float* kb = sm + KBUF((t) & 1);                                       \
        float* vb = sm + VBUF((t) & 1);                                       \
        _Pragma("unroll")                                                     \
        for (int it = 0; it < 8; it++) {                                      \
            int idx = tid + it * 128;              /* 0..1023 */              \
            int r = idx >> 5, cc = (idx & 31) << 2;                           \
            cp16(kb + r * KP + cc, Kn + (size_t)r * HD + cc);                 \
        }                                                                     \
        _Pragma("unroll")                                                     \
        for (int it = 0; it < 8; it++) {                                      \
            int idx = tid + it * 128;              /* 0..1023 */              \
            int d = idx >> 3, cc = (idx & 7) << 2;                            \
            cp16(vb + d * VTP + cc, Vtn + (size_t)d * SL + cc);               \
        }                                                                     \
    }

    F_FILL(0);
    CP_COMMIT();

    for (int kt = 0; kt < NKT; kt++) {
        const int buf = kt & 1;
        if (kt + 1 < NKT) {
            F_FILL(kt + 1);
            CP_COMMIT();
            CP_WAIT1();
        } else {
            CP_WAIT0();
        }
        __syncthreads();

        const uint32_t sK = sbase + (uint32_t)(KBUF(buf) * 4);
        const uint32_t sV = sbase + (uint32_t)(VBUF(buf) * 4);

        // ---- S = Q * K^T (16 rows x 32 keys) ----
        float sc[4][4] = {};
#pragma unroll
        for (int ks = 0; ks < 16; ks++) {
#pragma unroll
            for (int jp = 0; jp < 2; jp++) {
                uint32_t b0, b1, b2, b3;
                ldsm4(b0, b1, b2, b3,
                      sK + offK + (uint32_t)((jp * 16 * KP + 8 * ks) * 4));
                mma_tf32(sc[2 * jp],     qa[ks][0], qa[ks][1], qa[ks][2], qa[ks][3], b0, b1);
                mma_tf32(sc[2 * jp + 1], qa[ks][0], qa[ks][1], qa[ks][2], qa[ks][3], b2, b3);
            }
        }

        // ---- no-max softmax ----
#pragma unroll
        for (int j = 0; j < 4; j++) {
            float p0 = exp2f(sc[j][0]);
            float p1 = exp2f(sc[j][1]);
            float p2 = exp2f(sc[j][2]);
            float p3 = exp2f(sc[j][3]);
            l0 += p0 + p1; l1 += p2 + p3;
            sc[j][0] = to_tf32(p0); sc[j][1] = to_tf32(p1);
            sc[j][2] = to_tf32(p2); sc[j][3] = to_tf32(p3);
        }

        // ---- O += P * V (P c-frag -> a-frag via shuffles; V^T ldmatrix) ----
#pragma unroll
        for (int j = 0; j < 4; j++) {
            float v0 = __shfl_sync(0xffffffffu, sc[j][0], srcA);
            float v1 = __shfl_sync(0xffffffffu, sc[j][1], srcA);
            float v2 = __shfl_sync(0xffffffffu, sc[j][2], srcA);
            float v3 = __shfl_sync(0xffffffffu, sc[j][3], srcA);
            float w0 = __shfl_sync(0xffffffffu, sc[j][0], srcB);
            float w1 = __shfl_sync(0xffffffffu, sc[j][1], srcB);
            float w2 = __shfl_sync(0xffffffffu, sc[j][2], srcB);
            float w3 = __shfl_sync(0xffffffffu, sc[j][3], srcB);
            uint32_t a0 = __float_as_uint(odd ? v1 : v0);
            uint32_t a1 = __float_as_uint(odd ? v3 : v2);
            uint32_t a2 = __float_as_uint(odd ? w1 : w0);
            uint32_t a3 = __float_as_uint(odd ? w3 : w2);
#pragma unroll
            for (int jp = 0; jp < 8; jp++) {
                uint32_t b0, b1, b2, b3;
                ldsm4(b0, b1, b2, b3,
                      sV + offV + (uint32_t)((jp * 16 * VTP + 8 * j) * 4));
                mma_tf32(c[2 * jp],     a0, a1, a2, a3, b0, b1);
                mma_tf32(c[2 * jp + 1], a0, a1, a2, a3, b2, b3);
            }
        }
        __syncthreads();
    }

    // ---- final l reduction across the quad, normalize + write ----
    l0 += __shfl_xor_sync(0xffffffffu, l0, 1);
    l0 += __shfl_xor_sync(0xffffffffu, l0, 2);
    l1 += __shfl_xor_sync(0xffffffffu, l1, 1);
    l1 += __shfl_xor_sync(0xffffffffu, l1, 2);
    float inv0 = 1.0f / l0, inv1 = 1.0f / l1;
    int row0 = qt * FQT + wq + gid;
#pragma unroll
    for (int j2 = 0; j2 < 16; j2++) {
        int col = h * HD + 8 * j2 + 2 * tig;
        *(float2*)&g_attn[((size_t)b * SL + row0) * DIM + col] =
            make_float2(to_tf32(c[j2][0] * inv0), to_tf32(c[j2][1] * inv0));
        *(float2*)&g_attn[((size_t)b * SL + row0 + 8) * DIM + col] =
            make_float2(to_tf32(c[j2][2] * inv1), to_tf32(c[j2][3] * inv1));
    }
}

// ---------------------------------------------------------------------------
extern "C" void kernel_launch(void* const* d_in, const int* in_sizes, int n_in,
                              void* d_out, int out_size) {
    const float* x    = (const float*)d_in[0];
    const float* wqkv = (const float*)d_in[1];
    const float* wo   = (const float*)d_in[2];
    const float* qnw  = (const float*)d_in[3];
    const float* knw  = (const float*)d_in[4];
    const float* fcos = (const float*)d_in[5];
    const float* fsin = (const float*)d_in[6];
    float* out = (float*)d_out;

    void *p_qkv, *p_attn, *p_xc, *p_wqc, *p_woc;
    cudaGetSymbolAddress(&p_qkv,  g_qkv);
    cudaGetSymbolAddress(&p_attn, g_attn);
    cudaGetSymbolAddress(&p_xc,   g_xc);
    cudaGetSymbolAddress(&p_wqc,  g_wqc);
    cudaGetSymbolAddress(&p_woc,  g_woc);

    cudaFuncSetAttribute(flash_tf32,
                         cudaFuncAttributeMaxDynamicSharedMemorySize, FLASH_SMEM);
    cudaFuncSetAttribute(sgemm_tf32,
                         cudaFuncAttributeMaxDynamicSharedMemorySize, GEMM_SMEM);

    // 0) pre-convert all GEMM operands to tf32 (single launch)
    conv3_tf32<<<1184, 256>>>(x, wqkv, wo);

    // 1) QKV projection
    sgemm_tf32<<<dim3(QKV_N / 256, MROWS / 128), 256, GEMM_SMEM>>>(
        (const float*)p_xc, (const float*)p_wqc, (float*)p_qkv,
        MROWS, QKV_N, DIM);

    // 2) RMSNorm + RoPE (V transposed)
    norm_rope<<<MROWS * 24 / 8, 256>>>(qnw, knw, fcos, fsin);

    // 3) Flash attention (QT=64, 3 CTAs/SM)
    flash_tf32<<<dim3(SL / FQT, NH, BB), 128, FLASH_SMEM>>>();

    // 4) Output projection
    sgemm_tf32<<<dim3(DIM / 256, MROWS / 128), 256, GEMM_SMEM>>>(
        (const float*)p_attn, (const float*)p_woc, out, MROWS, DIM, DIM);
}

// round 15
// speedup vs baseline: 1.9034x; 1.8951x over previous
#include <cuda_runtime.h>
#include <cuda_fp16.h>
#include <math.h>
#include <stdint.h>

#define DIM   2048
#define NH    16
#define NKV   4
#define HD    128
#define BB    2
#define SL    2048
#define MROWS (BB*SL)                 // 4096
#define QKV_N ((NH + 2*NKV)*HD)       // 3072

// ---------------- scratch (static device globals; no allocations) -----------
__device__ float  g_qkv [MROWS * QKV_N];       // fp32 QKV output
__device__ __half g_q   [BB*NH *SL*HD];        // fp16 (qscale folded in)
__device__ __half g_k   [BB*NKV*SL*HD];        // fp16
__device__ __half g_v   [BB*NKV*SL*HD];        // fp16 [b][kv][s][d]
__device__ __half g_attn[MROWS * DIM];         // fp16 (O-proj A operand)
__device__ __half g_xh  [MROWS * DIM];         // fp16 copy of x
__device__ __half g_wqh [QKV_N * DIM];         // fp16 copy of wqkv
__device__ __half g_woh [DIM   * DIM];         // fp16 copy of wo

__device__ __forceinline__ uint32_t pack_h2(float lo, float hi) {
    __half2 h = __floats2half2_rn(lo, hi);
    return *(uint32_t*)&h;
}

__device__ __forceinline__ void mma_f16(float c[4],
                                        uint32_t a0, uint32_t a1,
                                        uint32_t a2, uint32_t a3,
                                        uint32_t b0, uint32_t b1) {
    asm volatile(
        "mma.sync.aligned.m16n8k16.row.col.f32.f16.f16.f32 "
        "{%0,%1,%2,%3},{%4,%5,%6,%7},{%8,%9},{%0,%1,%2,%3};"
        : "+f"(c[0]), "+f"(c[1]), "+f"(c[2]), "+f"(c[3])
        : "r"(a0), "r"(a1), "r"(a2), "r"(a3), "r"(b0), "r"(b1));
}

__device__ __forceinline__ void ldsm4(uint32_t& r0, uint32_t& r1,
                                      uint32_t& r2, uint32_t& r3,
                                      uint32_t addr) {
    asm volatile("ldmatrix.sync.aligned.m8n8.x4.shared.b16 {%0,%1,%2,%3}, [%4];"
                 : "=r"(r0), "=r"(r1), "=r"(r2), "=r"(r3) : "r"(addr));
}

__device__ __forceinline__ void ldsm4t(uint32_t& r0, uint32_t& r1,
                                       uint32_t& r2, uint32_t& r3,
                                       uint32_t addr) {
    asm volatile("ldmatrix.sync.aligned.m8n8.x4.trans.shared.b16 {%0,%1,%2,%3}, [%4];"
                 : "=r"(r0), "=r"(r1), "=r"(r2), "=r"(r3) : "r"(addr));
}

__device__ __forceinline__ void cp16(void* smem, const void* g) {
    uint32_t s = (uint32_t)__cvta_generic_to_shared(smem);
    asm volatile("cp.async.cg.shared.global [%0], [%1], 16;"
                 :: "r"(s), "l"(g) : "memory");
}
#define CP_COMMIT() asm volatile("cp.async.commit_group;" ::: "memory")
#define CP_WAIT1()  asm volatile("cp.async.wait_group 1;"  ::: "memory")
#define CP_WAIT0()  asm volatile("cp.async.wait_group 0;"  ::: "memory")

// ---------------------------------------------------------------------------
// fp32 -> fp16 convert for all three GEMM operands (one launch).
// ---------------------------------------------------------------------------
__global__ void conv3_f16(const float* __restrict__ x,
                          const float* __restrict__ wq,
                          const float* __restrict__ wo) {
    const int gs = gridDim.x * blockDim.x;
    const int t  = blockIdx.x * blockDim.x + threadIdx.x;
    const int n1 = MROWS * DIM / 4, n2 = QKV_N * DIM / 4, n3 = DIM * DIM / 4;

    for (int i = t; i < n1; i += gs) {
        float4 v = ((const float4*)x)[i];
        uint2 o = make_uint2(pack_h2(v.x, v.y), pack_h2(v.z, v.w));
        ((uint2*)g_xh)[i] = o;
    }
    for (int i = t; i < n2; i += gs) {
        float4 v = ((const float4*)wq)[i];
        uint2 o = make_uint2(pack_h2(v.x, v.y), pack_h2(v.z, v.w));
        ((uint2*)g_wqh)[i] = o;
    }
    for (int i = t; i < n3; i += gs) {
        float4 v = ((const float4*)wo)[i];
        uint2 o = make_uint2(pack_h2(v.x, v.y), pack_h2(v.z, v.w));
        ((uint2*)g_woh)[i] = o;
    }
}

// ---------------------------------------------------------------------------
// C(fp32) = A * B^T, fp16 m16n8k16 mma. CTA tile 128x256, warp tile 64x64,
// 3-stage cp.async, K-chunk 64 halves, pitch 72 halves (conflict-free LDSM).
// ---------------------------------------------------------------------------
#define GP      72
#define ASTG    (128 * GP)
#define BSTG    (256 * GP)
#define STG_TOT (ASTG + BSTG)                  // halves
#define GEMM_SMEM (3 * STG_TOT * 2)            // 165888 B

__global__ __launch_bounds__(256, 1)
void hgemm(const __half* __restrict__ A, const __half* __restrict__ B,
           float* __restrict__ C, int M, int N, int K) {
    extern __shared__ __half smh[];
    const uint32_t sbase = (uint32_t)__cvta_generic_to_shared(smh);

    const int tid  = threadIdx.x;
    const int lane = tid & 31;
    const int warp = tid >> 5;
    const int wm   = warp & 1;
    const int wn   = warp >> 1;
    const int gid  = lane >> 2;
    const int tig  = lane & 3;
    const int l8   = lane & 7;
    const int g8   = lane >> 3;

    const int m0 = blockIdx.y * 128;
    const int n0 = blockIdx.x * 256;
    const __half* Ab = A + (size_t)m0 * K;
    const __half* Bb = B + (size_t)n0 * K;

    const uint32_t offA = (uint32_t)(((wm * 64 + l8 + (g8 & 1) * 8) * GP
                                      + (g8 >> 1) * 8) * 2);
    const uint32_t offB = (uint32_t)(((wn * 64 + l8 + (g8 >> 1) * 8) * GP
                                      + (g8 & 1) * 8) * 2);

    float c[4][8][4] = {};
    const int nch = K / 64;

#define G_FILL(buf, k0)                                                       \
    {                                                                         \
        __half* As_ = smh + (size_t)(buf) * STG_TOT;                          \
        __half* Bs_ = As_ + ASTG;                                             \
        _Pragma("unroll")                                                     \
        for (int it = 0; it < 12; it++) {                                     \
            int idx = tid + it * 256;                                         \
            if (idx < 1024) {                                                 \
                int r = idx >> 3, cc = (idx & 7) << 3;                        \
                cp16(As_ + r * GP + cc, Ab + (size_t)r * K + (k0) + cc);      \
            } else {                                                          \
                int i2 = idx - 1024;                                          \
                int r = i2 >> 3, cc = (i2 & 7) << 3;                          \
                cp16(Bs_ + r * GP + cc, Bb + (size_t)r * K + (k0) + cc);      \
            }                                                                 \
        }                                                                     \
    }

    G_FILL(0, 0);  CP_COMMIT();
    G_FILL(1, 64); CP_COMMIT();

    for (int ch = 0; ch < nch; ch++) {
        const int buf = ch % 3;
        if (ch + 1 < nch) CP_WAIT1(); else CP_WAIT0();
        __syncthreads();

        const uint32_t sA = sbase + (uint32_t)(buf * STG_TOT) * 2u;
        const uint32_t sB = sA + (uint32_t)ASTG * 2u;

#pragma unroll
        for (int kk = 0; kk < 64; kk += 16) {
            uint32_t a[4][4], b[8][2];
#pragma unroll
            for (int f = 0; f < 4; f++)
                ldsm4(a[f][0], a[f][1], a[f][2], a[f][3],
                      sA + offA + (uint32_t)((f * 16 * GP + kk) * 2));
#pragma unroll
            for (int gp = 0; gp < 4; gp++)
                ldsm4(b[2 * gp][0], b[2 * gp][1],
                      b[2 * gp + 1][0], b[2 * gp + 1][1],
                      sB + offB + (uint32_t)((gp * 16 * GP + kk) * 2));
#pragma unroll
            for (int f = 0; f < 4; f++)
#pragma unroll
                for (int g = 0; g < 8; g++)
                    mma_f16(c[f][g], a[f][0], a[f][1], a[f][2], a[f][3],
                            b[g][0], b[g][1]);
        }

        if (ch + 2 < nch) { G_FILL((ch + 2) % 3, (ch + 2) * 64); CP_COMMIT(); }
    }

#pragma unroll
    for (int f = 0; f < 4; f++) {
        int row = m0 + wm * 64 + f * 16 + gid;
#pragma unroll
        for (int g = 0; g < 8; g++) {
            int col = n0 + wn * 64 + g * 8 + 2 * tig;
            *(float2*)&C[(size_t)row * N + col] =
                make_float2(c[f][g][0], c[f][g][1]);
            *(float2*)&C[(size_t)(row + 8) * N + col] =
                make_float2(c[f][g][2], c[f][g][3]);
        }
    }
}

// ---------------------------------------------------------------------------
// RMSNorm + RoPE, one warp per (token, head) vector; outputs fp16.
// Q outputs pre-scaled by log2e/sqrt(HD) (folded softmax scale).
// ---------------------------------------------------------------------------
__global__ __launch_bounds__(256)
void norm_rope(const float* __restrict__ qnw, const float* __restrict__ knw,
               const float* __restrict__ fcos, const float* __restrict__ fsin) {
    const int lane = threadIdx.x & 31;
    const int widx = blockIdx.x * 8 + (threadIdx.x >> 5);
    const int hh = widx % 24;
    const int m  = widx / 24;
    const int b  = m / SL;
    const int s  = m % SL;
    const int d4 = lane * 4;
    const float qscale = 1.4426950408889634f * rsqrtf((float)HD);

    float4 v = *(const float4*)&g_qkv[(size_t)m * QKV_N + hh * HD + d4];

    if (hh < 20) {
        float ssq = v.x * v.x + v.y * v.y + v.z * v.z + v.w * v.w;
#pragma unroll
        for (int o = 16; o > 0; o >>= 1)
            ssq += __shfl_xor_sync(0xffffffffu, ssq, o);
        float r = rsqrtf(ssq * (1.0f / HD) + 1.1920929e-07f);

        const float* w = (hh < NH) ? qnw : knw;
        float4 wv = *(const float4*)&w[d4];
        float x0 = v.x * r * wv.x, x1 = v.y * r * wv.y;
        float x2 = v.z * r * wv.z, x3 = v.w * r * wv.w;

        float4 fc = *(const float4*)&fcos[s * HD + d4];
        float4 fs = *(const float4*)&fsin[s * HD + d4];
        float o0 = x0 * fc.x - x1 * fs.x;
        float o1 = x1 * fc.y + x0 * fs.y;
        float o2 = x2 * fc.z - x3 * fs.z;
        float o3 = x3 * fc.w + x2 * fs.w;

        if (hh < NH) {
            o0 *= qscale; o1 *= qscale; o2 *= qscale; o3 *= qscale;
            uint2 o = make_uint2(pack_h2(o0, o1), pack_h2(o2, o3));
            *(uint2*)&g_q[(((size_t)b * NH + hh) * SL + s) * HD + d4] = o;
        } else {
            uint2 o = make_uint2(pack_h2(o0, o1), pack_h2(o2, o3));
            *(uint2*)&g_k[(((size_t)b * NKV + (hh-16)) * SL + s) * HD + d4] = o;
        }
    } else {
        uint2 o = make_uint2(pack_h2(v.x, v.y), pack_h2(v.z, v.w));
        *(uint2*)&g_v[(((size_t)b * NKV + (hh-20)) * SL + s) * HD + d4] = o;
    }
}

// ---------------------------------------------------------------------------
// Flash attention, fp16 m16n8k16, NO-MAX softmax with -1 exponent shift
// (P' = 2^(s-1) <= 41285 < fp16 max; normalization cancels the shift).
// QT=128 (8 warps x 16 rows), KT=64, cp.async double-buffered K/V.
// P C-frag == fp16 A-frag layout -> no shuffles in PV; V via ldmatrix.trans.
// ---------------------------------------------------------------------------
#define FQT  128
#define FKT  64
#define FP   136                               // halves pitch
#define KBUF(b) ((b) * FKT * FP)
#define VBUF(b) (2 * FKT * FP + (b) * FKT * FP)
#define FLASH_SMEM (4 * FKT * FP * 2)          // 69632 B

__global__ __launch_bounds__(256)
void flash_f16() {
    extern __shared__ __half smh[];
    const uint32_t sbase = (uint32_t)__cvta_generic_to_shared(smh);

    const int tid  = threadIdx.x;
    const int lane = tid & 31;
    const int warp = tid >> 5;
    const int gid  = lane >> 2;
    const int tig  = lane & 3;
    const int l8   = lane & 7;
    const int g8   = lane >> 3;
    const int wq   = warp * 16;

    const int qt = blockIdx.x, h = blockIdx.y, b = blockIdx.z;
    const int kvh = h >> 2;

    const __half* Qg = g_q + (((size_t)b * NH  + h  ) * SL + qt * FQT) * HD;
    const __half* Kg = g_k + (((size_t)b * NKV + kvh) * SL) * HD;
    const __half* Vg = g_v + (((size_t)b * NKV + kvh) * SL) * HD;

    // ---- stage Q into the (aliased) two K buffers via cp.async ----
#pragma unroll
    for (int it = 0; it < 8; it++) {
        int idx = tid + it * 256;               // 0..2047 16B chunks
        int r = idx >> 4, cc = (idx & 15) << 3;
        cp16(smh + r * FP + cc, Qg + (size_t)r * HD + cc);
    }
    CP_COMMIT(); CP_WAIT0();
    __syncthreads();

    const uint32_t offQ = (uint32_t)(((wq + l8 + (g8 & 1) * 8) * FP
                                      + (g8 >> 1) * 8) * 2);
    uint32_t qa[8][4];
#pragma unroll
    for (int ks = 0; ks < 8; ks++)
        ldsm4(qa[ks][0], qa[ks][1], qa[ks][2], qa[ks][3],
              sbase + offQ + (uint32_t)(ks * 16 * 2));
    __syncthreads();   // Q reads done before K fills overwrite the alias

    float c[16][4] = {};
    float l0 = 0.0f, l1 = 0.0f;

    const uint32_t offK = (uint32_t)(((l8 + (g8 >> 1) * 8) * FP
                                      + (g8 & 1) * 8) * 2);
    const uint32_t offV = (uint32_t)(((l8 + (g8 & 1) * 8) * FP
                                      + (g8 >> 1) * 8) * 2);

    const int NKT = SL / FKT;                  // 32

#define F_FILL(t)                                                             \
    {                                                                         \
        const __half* Kn = Kg + (size_t)(t) * FKT * HD;                       \
        const __half* Vn = Vg + (size_t)(t) * FKT * HD;                       \
        __half* kb = smh + KBUF((t) & 1);                                     \
        __half* vb = smh + VBUF((t) & 1);                                     \
        _Pragma("unroll")                                                     \
        for (int it = 0; it < 4; it++) {                                      \
            int idx = tid + it * 256;          /* 0..1023 */                  \
            int r = idx >> 4, cc = (idx & 15) << 3;                           \
            cp16(kb + r * FP + cc, Kn + (size_t)r * HD + cc);                 \
            cp16(vb + r * FP + cc, Vn + (size_t)r * HD + cc);                 \
        }                                                                     \
    }

    F_FILL(0);
    CP_COMMIT();

    for (int kt = 0; kt < NKT; kt++) {
        const int buf = kt & 1;
        if (kt + 1 < NKT) {
            F_FILL(kt + 1);
            CP_COMMIT();
            CP_WAIT1();
        } else {
            CP_WAIT0();
        }
        __syncthreads();

        const uint32_t sK = sbase + (uint32_t)(KBUF(buf) * 2);
        const uint32_t sV = sbase + (uint32_t)(VBUF(buf) * 2);

        // ---- S = Q * K^T : 8 k16-slabs x 8 key-groups ----
        float sc[8][4] = {};
#pragma unroll
        for (int ks = 0; ks < 8; ks++) {
#pragma unroll
            for (int jp = 0; jp < 4; jp++) {
                uint32_t b0, b1, b2, b3;
                ldsm4(b0, b1, b2, b3,
                      sK + offK + (uint32_t)((jp * 16 * FP + ks * 16) * 2));
                mma_f16(sc[2 * jp],     qa[ks][0], qa[ks][1], qa[ks][2], qa[ks][3], b0, b1);
                mma_f16(sc[2 * jp + 1], qa[ks][0], qa[ks][1], qa[ks][2], qa[ks][3], b2, b3);
            }
        }

        // ---- softmax (exp2, -1 shift) + pack P into fp16 A-frags ----
        uint32_t pa[4][4];
#pragma unroll
        for (int s = 0; s < 4; s++) {
            float pa0 = exp2f(sc[2*s][0] - 1.0f);
            float pa1 = exp2f(sc[2*s][1] - 1.0f);
            float pa2 = exp2f(sc[2*s][2] - 1.0f);
            float pa3 = exp2f(sc[2*s][3] - 1.0f);
            float pb0 = exp2f(sc[2*s+1][0] - 1.0f);
            float pb1 = exp2f(sc[2*s+1][1] - 1.0f);
            float pb2 = exp2f(sc[2*s+1][2] - 1.0f);
            float pb3 = exp2f(sc[2*s+1][3] - 1.0f);
            l0 += pa0 + pa1 + pb0 + pb1;
            l1 += pa2 + pa3 + pb2 + pb3;
            pa[s][0] = pack_h2(pa0, pa1);      // row gid,   keys slab lo-group
            pa[s][1] = pack_h2(pa2, pa3);      // row gid+8, lo-group
            pa[s][2] = pack_h2(pb0, pb1);      // row gid,   hi-group
            pa[s][3] = pack_h2(pb2, pb3);      // row gid+8, hi-group
        }

        // ---- O += P * V : 4 key-slabs x 8 d-group-pairs (ldmatrix.trans) ---
#pragma unroll
        for (int j = 0; j < 4; j++) {
#pragma unroll
            for (int dp = 0; dp < 8; dp++) {
                uint32_t b0, b1, b2, b3;
                ldsm4t(b0, b1, b2, b3,
                       sV + offV + (uint32_t)((j * 16 * FP + dp * 16) * 2));
                mma_f16(c[2 * dp],     pa[j][0], pa[j][1], pa[j][2], pa[j][3], b0, b1);
                mma_f16(c[2 * dp + 1], pa[j][0], pa[j][1], pa[j][2], pa[j][3], b2, b3);
            }
        }
        __syncthreads();
    }

    // ---- final l reduction across the quad, normalize + write fp16 ----
    l0 += __shfl_xor_sync(0xffffffffu, l0, 1);
    l0 += __shfl_xor_sync(0xffffffffu, l0, 2);
    l1 += __shfl_xor_sync(0xffffffffu, l1, 1);
    l1 += __shfl_xor_sync(0xffffffffu, l1, 2);
    float inv0 = 1.0f / l0, inv1 = 1.0f / l1;
    int row0 = qt * FQT + wq + gid;
#pragma unroll
    for (int j2 = 0; j2 < 16; j2++) {
        int col = h * HD + 8 * j2 + 2 * tig;
        *(uint32_t*)&g_attn[((size_t)b * SL + row0) * DIM + col] =
            pack_h2(c[j2][0] * inv0, c[j2][1] * inv0);
        *(uint32_t*)&g_attn[((size_t)b * SL + row0 + 8) * DIM + col] =
            pack_h2(c[j2][2] * inv1, c[j2][3] * inv1);
    }
}

// ---------------------------------------------------------------------------
extern "C" void kernel_launch(void* const* d_in, const int* in_sizes, int n_in,
                              void* d_out, int out_size) {
    const float* x    = (const float*)d_in[0];
    const float* wqkv = (const float*)d_in[1];
    const float* wo   = (const float*)d_in[2];
    const float* qnw  = (const float*)d_in[3];
    const float* knw  = (const float*)d_in[4];
    const float* fcos = (const float*)d_in[5];
    const float* fsin = (const float*)d_in[6];
    float* out = (float*)d_out;

    void *p_qkv, *p_attn, *p_xh, *p_wqh, *p_woh;
    cudaGetSymbolAddress(&p_qkv,  g_qkv);
    cudaGetSymbolAddress(&p_attn, g_attn);
    cudaGetSymbolAddress(&p_xh,   g_xh);
    cudaGetSymbolAddress(&p_wqh,  g_wqh);
    cudaGetSymbolAddress(&p_woh,  g_woh);

    cudaFuncSetAttribute(flash_f16,
                         cudaFuncAttributeMaxDynamicSharedMemorySize, FLASH_SMEM);
    cudaFuncSetAttribute(hgemm,
                         cudaFuncAttributeMaxDynamicSharedMemorySize, GEMM_SMEM);

    // 0) convert all GEMM operands to fp16 (single launch)
    conv3_f16<<<1184, 256>>>(x, wqkv, wo);

    // 1) QKV projection (fp16 mma)
    hgemm<<<dim3(QKV_N / 256, MROWS / 128), 256, GEMM_SMEM>>>(
        (const __half*)p_xh, (const __half*)p_wqh, (float*)p_qkv,
        MROWS, QKV_N, DIM);

    // 2) RMSNorm + RoPE (fp16 outputs, qscale folded)
    norm_rope<<<MROWS * 24 / 8, 256>>>(qnw, knw, fcos, fsin);

    // 3) Flash attention (fp16 mma)
    flash_f16<<<dim3(SL / FQT, NH, BB), 256, FLASH_SMEM>>>();

    // 4) Output projection (fp16 mma)
    hgemm<<<dim3(DIM / 256, MROWS / 128), 256, GEMM_SMEM>>>(
        (const __half*)p_attn, (const __half*)p_woh, out, MROWS, DIM, DIM);
}